// round 3
// baseline (speedup 1.0000x reference)
#include <cuda_runtime.h>
#include <math.h>

// Problem constants
#define HDIM 128
#define FDIM 64
#define THDIM 384              // 3*H
#define IS3  0.5773502691896258f      // 1/sqrt(3)
#define ISH  0.08838834764831845f     // 1/sqrt(128)
#define SSC  1.6666666666666667f      // 1/0.6

#define MAXN 50000
#define MAXE 400000
#define EBS 8                  // edges per warp-group in sorted edge kernel

typedef unsigned long long ull;

// Scratch (device globals: allocation-free)
__device__ float g_xd  [MAXN * THDIM];
__device__ float g_h1  [MAXN * FDIM];
__device__ float g_xh  [MAXN * THDIM];
__device__ float g_lvec[MAXN * 3 * HDIM];
__device__ int   g_deg [MAXN];
__device__ int   g_off [MAXN];          // scan output, consumed as cursor by fill
__device__ int   g_elist[MAXE];

// ---------------------------------------------------------------------------
// Packed fp32x2 helpers
// ---------------------------------------------------------------------------
__device__ __forceinline__ ull pk(float lo, float hi) {
    ull r; asm("mov.b64 %0, {%1, %2};" : "=l"(r) : "f"(lo), "f"(hi)); return r;
}
__device__ __forceinline__ void upk(ull v, float& lo, float& hi) {
    asm("mov.b64 {%0, %1}, %2;" : "=f"(lo), "=f"(hi) : "l"(v));
}
__device__ __forceinline__ void fma2(ull& d, ull a, ull b) {
    asm("fma.rn.f32x2 %0, %1, %2, %0;" : "+l"(d) : "l"(a), "l"(b));
}

// ---------------------------------------------------------------------------
// Small utility kernels
// ---------------------------------------------------------------------------
__global__ void zero_kernel(float4* __restrict__ p, long n4) {
    long i = (long)blockIdx.x * blockDim.x + threadIdx.x;
    if (i < n4) p[i] = make_float4(0.f, 0.f, 0.f, 0.f);
}
__global__ void zeroi_kernel(int* __restrict__ p, int n) {
    int i = blockIdx.x * blockDim.x + threadIdx.x;
    if (i < n) p[i] = 0;
}
__global__ void hist_kernel(const int* __restrict__ ei, int* __restrict__ deg, int E) {
    int e = blockIdx.x * blockDim.x + threadIdx.x;
    if (e < E) atomicAdd(&deg[ei[e]], 1);
}
// single-CTA exclusive scan (N up to ~1M with chunking)
__global__ void scan_kernel(const int* __restrict__ deg, int* __restrict__ off, int Nn) {
    __shared__ int s[1024];
    int t = threadIdx.x;
    int chunk = (Nn + 1023) / 1024;
    int lo = t * chunk, hi = min(lo + chunk, Nn);
    int sum = 0;
    for (int k = lo; k < hi; k++) sum += deg[k];
    s[t] = sum;
    __syncthreads();
    for (int d = 1; d < 1024; d <<= 1) {
        int x = (t >= d) ? s[t - d] : 0;
        __syncthreads();
        s[t] += x;
        __syncthreads();
    }
    int run = s[t] - sum;   // exclusive prefix of this chunk
    for (int k = lo; k < hi; k++) { off[k] = run; run += deg[k]; }
}
__global__ void fill_kernel(const int* __restrict__ ei, int* __restrict__ cursor,
                            int* __restrict__ elist, int E) {
    int e = blockIdx.x * blockDim.x + threadIdx.x;
    if (e < E) {
        int slot = atomicAdd(&cursor[ei[e]], 1);
        elist[slot] = e;
    }
}

// ---------------------------------------------------------------------------
// fp32 SGEMM with FFMA2 inner product: C = act(A @ W + bias)
// ---------------------------------------------------------------------------
template<int BM, int BN, int BK, int TM, int TN, int ACT, int HASB>
__global__ void __launch_bounds__(256)
sgemm_kernel(const float* __restrict__ A, const float* __restrict__ W,
             const float* __restrict__ bias, float* __restrict__ C,
             int M, int N, int K)
{
    __shared__ float As[BK][BM];
    __shared__ float Ws[BK][BN];

    const int tid  = threadIdx.x;
    const int row0 = blockIdx.x * BM;
    const int col0 = blockIdx.y * BN;
    const int tx   = tid % (BN / TN);
    const int ty   = tid / (BN / TN);

    const int aRow = tid / (BK / 4);
    const int aCol = (tid % (BK / 4)) * 4;
    const int wRow = tid / (BN / 4);
    const int wCol = (tid % (BN / 4)) * 4;

    ull acc2[TM][TN / 2];
#pragma unroll
    for (int i = 0; i < TM; i++)
#pragma unroll
        for (int j = 0; j < TN / 2; j++) acc2[i][j] = 0ULL;

    for (int k0 = 0; k0 < K; k0 += BK) {
#pragma unroll
        for (int r = 0; r < BM; r += 256 / (BK / 4)) {
            int gr = row0 + aRow + r;
            float4 v = make_float4(0.f, 0.f, 0.f, 0.f);
            if (gr < M)
                v = *(const float4*)(A + (size_t)gr * K + k0 + aCol);
            As[aCol + 0][aRow + r] = v.x;
            As[aCol + 1][aRow + r] = v.y;
            As[aCol + 2][aRow + r] = v.z;
            As[aCol + 3][aRow + r] = v.w;
        }
#pragma unroll
        for (int r = 0; r < BK; r += 256 / (BN / 4)) {
            *(float4*)&Ws[wRow + r][wCol] =
                *(const float4*)(W + (size_t)(k0 + wRow + r) * N + col0 + wCol);
        }
        __syncthreads();

#pragma unroll
        for (int k = 0; k < BK; k++) {
            float am[TM], wn[TN];
#pragma unroll
            for (int i = 0; i < TM; i += 4)
                *(float4*)&am[i] = *(const float4*)&As[k][ty * TM + i];
#pragma unroll
            for (int j = 0; j < TN; j += 4)
                *(float4*)&wn[j] = *(const float4*)&Ws[k][tx * TN + j];
            ull wn2[TN / 2];
#pragma unroll
            for (int j = 0; j < TN / 2; j++) wn2[j] = pk(wn[2 * j], wn[2 * j + 1]);
#pragma unroll
            for (int i = 0; i < TM; i++) {
                ull a2 = pk(am[i], am[i]);
#pragma unroll
                for (int j = 0; j < TN / 2; j++)
                    fma2(acc2[i][j], a2, wn2[j]);
            }
        }
        __syncthreads();
    }

    float bv[TN];
#pragma unroll
    for (int j = 0; j < TN; j++)
        bv[j] = HASB ? bias[col0 + tx * TN + j] : 0.f;

#pragma unroll
    for (int i = 0; i < TM; i++) {
        int gr = row0 + ty * TM + i;
        if (gr >= M) continue;
#pragma unroll
        for (int j = 0; j < TN; j += 4) {
            float t[4];
            upk(acc2[i][j / 2],     t[0], t[1]);
            upk(acc2[i][j / 2 + 1], t[2], t[3]);
#pragma unroll
            for (int q = 0; q < 4; q++) {
                float v = t[q] + bv[j + q];
                if (ACT == 1) v = v / (1.f + expf(-v)) * SSC;  // ScaledSiLU
                t[q] = v;
            }
            *(float4*)(C + (size_t)gr * N + col0 + tx * TN + j) =
                make_float4(t[0], t[1], t[2], t[3]);
        }
    }
}

// ---------------------------------------------------------------------------
// Vectorized global reduction
// ---------------------------------------------------------------------------
__device__ __forceinline__ void red4(float* p, float4 v) {
    asm volatile("red.global.add.v4.f32 [%0], {%1,%2,%3,%4};"
                 :: "l"(p), "f"(v.x), "f"(v.y), "f"(v.z), "f"(v.w)
                 : "memory");
}

// ---------------------------------------------------------------------------
// Sorted fused edge kernel.
// Edges pre-sorted by destination i (g_elist). Each warp handles EBS=8
// consecutive sorted edges: batched rbf GEMM from smem W (FFMA2, operands
// pre-packed so the hot loop is LDS + FFMA2 only), then segmented register
// accumulation over destination runs, flushing red4 once per distinct i.
// ---------------------------------------------------------------------------
__global__ void __launch_bounds__(256, 1)
edge_sorted_kernel(const float* __restrict__ xh, const float* __restrict__ xd,
                   const float* __restrict__ vec, const float* __restrict__ efeat,
                   const float* __restrict__ We, const float* __restrict__ be,
                   const float* __restrict__ ev,
                   const int* __restrict__ ej, const int* __restrict__ ei,
                   const int* __restrict__ elist,
                   float* __restrict__ dx, float* __restrict__ dvec, int E)
{
    extern __shared__ float smem[];
    float* Ws = smem;                                   // [64][384] floats
    ull*   efs_all = (ull*)(smem + 64 * THDIM);         // [8 warps][EBS][64] packed (v,v)

    const int tid = threadIdx.x;

    // cooperative load of W_edge into smem
    for (int idx = tid; idx < 64 * THDIM / 4; idx += 256)
        ((float4*)Ws)[idx] = ((const float4*)We)[idx];
    __syncthreads();

    const int warp = tid >> 5;
    const int q    = tid & 31;
    ull* efs = efs_all + warp * (EBS * 64);

    const float4 be0 = *(const float4*)(be + 4 * q);
    const float4 be1 = *(const float4*)(be + HDIM + 4 * q);
    const float4 be2 = *(const float4*)(be + 2 * HDIM + 4 * q);

    const int nG = (E + EBS - 1) / EBS;
    const int stride = gridDim.x * 8;

    for (int g = blockIdx.x * 8 + warp; g < nG; g += stride) {
        const int base = g * EBS;
        const int nval = min(EBS, E - base);

        // edge metadata (uniform across warp; L1-broadcast loads)
        int eidv[EBS], jv[EBS], iv[EBS];
#pragma unroll
        for (int s = 0; s < EBS; s++) {
            int e = elist[base + min(s, nval - 1)];
            eidv[s] = e;
            jv[s] = ej[e];
            iv[s] = ei[e];
        }

        // stage edge_feat rows, duplicated (v,v) for FFMA2 broadcast operand
#pragma unroll
        for (int s = 0; s < EBS; s++) {
            float2 v = *(const float2*)(efeat + (size_t)eidv[s] * FDIM + 2 * q);
            efs[s * 64 + 2 * q]     = pk(v.x, v.x);
            efs[s * 64 + 2 * q + 1] = pk(v.y, v.y);
        }
        __syncwarp();

        // batched rbf accumulation
        ull acc[EBS][6];
#pragma unroll
        for (int s = 0; s < EBS; s++)
#pragma unroll
            for (int c = 0; c < 6; c++) acc[s][c] = 0ULL;

#pragma unroll 8
        for (int k = 0; k < 64; k++) {
            const float* wrow = Ws + k * THDIM + 4 * q;
            ulonglong2 w0 = *(const ulonglong2*)(wrow);
            ulonglong2 w1 = *(const ulonglong2*)(wrow + HDIM);
            ulonglong2 w2 = *(const ulonglong2*)(wrow + 2 * HDIM);
#pragma unroll
            for (int s = 0; s < EBS; s++) {
                ull ef2 = efs[s * 64 + k];       // LDS.64 broadcast
                fma2(acc[s][0], ef2, w0.x);
                fma2(acc[s][1], ef2, w0.y);
                fma2(acc[s][2], ef2, w1.x);
                fma2(acc[s][3], ef2, w1.y);
                fma2(acc[s][4], ef2, w2.x);
                fma2(acc[s][5], ef2, w2.y);
            }
        }

        // segmented epilogue over destination runs
        float4 rv0, rv1, rv2, rx;
        int cur_i = -1;
        const int h0 = q * 4;

        for (int s = 0; s < nval; s++) {
            int j = jv[s], i = iv[s], eg = eidv[s];

            float r0[4], r1[4], r2[4];
            upk(acc[s][0], r0[0], r0[1]); upk(acc[s][1], r0[2], r0[3]);
            upk(acc[s][2], r1[0], r1[1]); upk(acc[s][3], r1[2], r1[3]);
            upk(acc[s][4], r2[0], r2[1]); upk(acc[s][5], r2[2], r2[3]);
            r0[0] += be0.x; r0[1] += be0.y; r0[2] += be0.z; r0[3] += be0.w;
            r1[0] += be1.x; r1[1] += be1.y; r1[2] += be1.z; r1[3] += be1.w;
            r2[0] += be2.x; r2[1] += be2.y; r2[2] += be2.z; r2[3] += be2.w;

            const float4* xhj = (const float4*)(xh + (size_t)j * THDIM);
            const float4* xdj = (const float4*)(xd + (size_t)j * THDIM);
            const float4* xdi = (const float4*)(xd + (size_t)i * THDIM);

            float4 m0, m1, m2;
            {
                float4 a = xhj[q],      b1 = xdj[q],      b2 = xdi[q];
                m0.x = a.x * (b1.x + b2.x) * r0[0] * IS3;
                m0.y = a.y * (b1.y + b2.y) * r0[1] * IS3;
                m0.z = a.z * (b1.z + b2.z) * r0[2] * IS3;
                m0.w = a.w * (b1.w + b2.w) * r0[3] * IS3;
            }
            {
                float4 a = xhj[32 + q], b1 = xdj[32 + q], b2 = xdi[32 + q];
                m1.x = a.x * (b1.x + b2.x) * r1[0] * IS3;
                m1.y = a.y * (b1.y + b2.y) * r1[1] * IS3;
                m1.z = a.z * (b1.z + b2.z) * r1[2] * IS3;
                m1.w = a.w * (b1.w + b2.w) * r1[3] * IS3;
            }
            {
                float4 a = xhj[64 + q], b1 = xdj[64 + q], b2 = xdi[64 + q];
                m2.x = a.x * (b1.x + b2.x) * r2[0] * IS3;
                m2.y = a.y * (b1.y + b2.y) * r2[1] * IS3;
                m2.z = a.z * (b1.z + b2.z) * r2[2] * IS3;
                m2.w = a.w * (b1.w + b2.w) * r2[3] * IS3;
            }

            float evd0 = ev[(size_t)eg * 3 + 0];
            float evd1 = ev[(size_t)eg * 3 + 1];
            float evd2 = ev[(size_t)eg * 3 + 2];

            const float4* vj = (const float4*)(vec + (size_t)j * THDIM);
            float4 v0 = vj[q], v1 = vj[32 + q], v2 = vj[64 + q];

            float4 c0, c1, c2;
            c0.x = (m0.x * v0.x + m1.x * evd0) * ISH;
            c0.y = (m0.y * v0.y + m1.y * evd0) * ISH;
            c0.z = (m0.z * v0.z + m1.z * evd0) * ISH;
            c0.w = (m0.w * v0.w + m1.w * evd0) * ISH;
            c1.x = (m0.x * v1.x + m1.x * evd1) * ISH;
            c1.y = (m0.y * v1.y + m1.y * evd1) * ISH;
            c1.z = (m0.z * v1.z + m1.z * evd1) * ISH;
            c1.w = (m0.w * v1.w + m1.w * evd1) * ISH;
            c2.x = (m0.x * v2.x + m1.x * evd2) * ISH;
            c2.y = (m0.y * v2.y + m1.y * evd2) * ISH;
            c2.z = (m0.z * v2.z + m1.z * evd2) * ISH;
            c2.w = (m0.w * v2.w + m1.w * evd2) * ISH;

            if (i != cur_i) {
                if (cur_i >= 0) {
                    float* dvb = dvec + (size_t)cur_i * THDIM;
                    red4(dvb + h0, rv0);
                    red4(dvb + HDIM + h0, rv1);
                    red4(dvb + 2 * HDIM + h0, rv2);
                    red4(dx + (size_t)cur_i * HDIM + h0, rx);
                }
                cur_i = i;
                rv0 = c0; rv1 = c1; rv2 = c2; rx = m2;
            } else {
                rv0.x += c0.x; rv0.y += c0.y; rv0.z += c0.z; rv0.w += c0.w;
                rv1.x += c1.x; rv1.y += c1.y; rv1.z += c1.z; rv1.w += c1.w;
                rv2.x += c2.x; rv2.y += c2.y; rv2.z += c2.z; rv2.w += c2.w;
                rx.x += m2.x;  rx.y += m2.y;  rx.z += m2.z;  rx.w += m2.w;
            }
        }
        if (cur_i >= 0) {
            float* dvb = dvec + (size_t)cur_i * THDIM;
            red4(dvb + h0, rv0);
            red4(dvb + HDIM + h0, rv1);
            red4(dvb + 2 * HDIM + h0, rv2);
            red4(dx + (size_t)cur_i * HDIM + h0, rx);
        }
        __syncwarp();
    }
}

// ---------------------------------------------------------------------------
// Vector activation epilogue
// ---------------------------------------------------------------------------
__global__ void combine_kernel(const float* __restrict__ lvec,
                               const float* __restrict__ Wg,
                               float* __restrict__ dvec, int Nn)
{
    __shared__ float wg_s[HDIM];
    __shared__ float red_s[4][3];
    int t = threadIdx.x;   // 128
    wg_s[t] = Wg[t];
    __syncthreads();

    for (int n = blockIdx.x; n < Nn; n += gridDim.x) {
        const float* vr = dvec + (size_t)n * THDIM;
        float v0 = vr[t], v1 = vr[HDIM + t], v2 = vr[2 * HDIM + t];
        float w = wg_s[t];
        float p0 = v0 * w, p1 = v1 * w, p2 = v2 * w;
#pragma unroll
        for (int off = 16; off > 0; off >>= 1) {
            p0 += __shfl_xor_sync(0xffffffffu, p0, off);
            p1 += __shfl_xor_sync(0xffffffffu, p1, off);
            p2 += __shfl_xor_sync(0xffffffffu, p2, off);
        }
        if ((t & 31) == 0) {
            red_s[t >> 5][0] = p0;
            red_s[t >> 5][1] = p1;
            red_s[t >> 5][2] = p2;
        }
        __syncthreads();
        float gv0 = red_s[0][0] + red_s[1][0] + red_s[2][0] + red_s[3][0];
        float gv1 = red_s[0][1] + red_s[1][1] + red_s[2][1] + red_s[3][1];
        float gv2 = red_s[0][2] + red_s[1][2] + red_s[2][2] + red_s[3][2];

        const float* lv = lvec + (size_t)n * THDIM;
        float l0 = lv[t], l1 = lv[HDIM + t], l2 = lv[2 * HDIM + t];
        float dot = l0 * gv0 + l1 * gv1 + l2 * gv2;

        float* o = dvec + (size_t)n * THDIM;
        if (dot >= 0.f) {
            o[t] = l0; o[HDIM + t] = l1; o[2 * HDIM + t] = l2;
        } else {
            o[t]            = (l0 + gv0) * 0.5f;
            o[HDIM + t]     = (l1 + gv1) * 0.5f;
            o[2 * HDIM + t] = (l2 + gv2) * 0.5f;
        }
        __syncthreads();
    }
}

// ---------------------------------------------------------------------------
// Launch
// ---------------------------------------------------------------------------
extern "C" void kernel_launch(void* const* d_in, const int* in_sizes, int n_in,
                              void* d_out, int out_size)
{
    const float* x     = (const float*)d_in[0];
    const float* xdef  = (const float*)d_in[1];
    const float* vec   = (const float*)d_in[2];
    const float* efeat = (const float*)d_in[3];
    const float* evec  = (const float*)d_in[4];
    const int*   eidx  = (const int*)  d_in[5];
    const float* Wd    = (const float*)d_in[6];
    const float* bd    = (const float*)d_in[7];
    const float* W1    = (const float*)d_in[8];
    const float* b1    = (const float*)d_in[9];
    const float* W2    = (const float*)d_in[10];
    const float* b2    = (const float*)d_in[11];
    const float* We    = (const float*)d_in[12];
    const float* be    = (const float*)d_in[13];
    const float* Wl    = (const float*)d_in[14];
    const float* Wg    = (const float*)d_in[15];

    int N = in_sizes[0] / HDIM;     // 50000
    int E = in_sizes[4] / 3;        // 400000

    float *p_xd, *p_h1, *p_xh, *p_lvec;
    int *p_deg, *p_off, *p_elist;
    cudaGetSymbolAddress((void**)&p_xd,    g_xd);
    cudaGetSymbolAddress((void**)&p_h1,    g_h1);
    cudaGetSymbolAddress((void**)&p_xh,    g_xh);
    cudaGetSymbolAddress((void**)&p_lvec,  g_lvec);
    cudaGetSymbolAddress((void**)&p_deg,   g_deg);
    cudaGetSymbolAddress((void**)&p_off,   g_off);
    cudaGetSymbolAddress((void**)&p_elist, g_elist);

    float* dx   = (float*)d_out;
    float* dvec = (float*)d_out + (size_t)N * HDIM;

    const int* ej = eidx;
    const int* ei = eidx + E;

    // 0) zero accumulators + CSR build (counting sort of edges by dest i)
    long n4 = (long)out_size / 4;
    zero_kernel<<<(unsigned)((n4 + 255) / 256), 256>>>((float4*)d_out, n4);
    zeroi_kernel<<<(N + 255) / 256, 256>>>(p_deg, N);
    hist_kernel<<<(E + 255) / 256, 256>>>(ei, p_deg, E);
    scan_kernel<<<1, 1024>>>(p_deg, p_off, N);
    fill_kernel<<<(E + 255) / 256, 256>>>(ei, p_off, p_elist, E);

    dim3 gN((N + 127) / 128, 3);
    dim3 gN1((N + 127) / 128, 1);
    dim3 gL((3 * N + 127) / 128, 1);

    // 1) xd = x_defect @ W_defect + b                   [N,384], K=128
    sgemm_kernel<128,128,16,8,8,0,1><<<gN, 256>>>(xdef, Wd, bd, p_xd, N, THDIM, HDIM);
    // 2) h1 = ScaledSiLU(x @ W_x1 + b)                  [N,64],  K=128
    sgemm_kernel<128, 64,16,8,4,1,1><<<gN1,256>>>(x, W1, b1, p_h1, N, FDIM, HDIM);
    // 3) xh = h1 @ W_x2 + b                             [N,384], K=64
    sgemm_kernel<128,128,16,8,8,0,1><<<gN, 256>>>(p_h1, W2, b2, p_xh, N, THDIM, FDIM);

    // 4) sorted fused edge kernel: rbf GEMM + message + segmented scatter-add
    int smem_bytes = 64 * THDIM * 4 + 8 * EBS * 64 * 8;   // 96KB + 32KB
    cudaFuncSetAttribute(edge_sorted_kernel,
                         cudaFuncAttributeMaxDynamicSharedMemorySize, smem_bytes);
    edge_sorted_kernel<<<296, 256, smem_bytes>>>(
        p_xh, p_xd, vec, efeat, We, be, evec, ej, ei, p_elist, dx, dvec, E);

    // 5) lvec = d_vec_raw @ W_lvec                      [3N,128], K=128
    sgemm_kernel<128,128,16,8,8,0,0><<<gL, 256>>>(dvec, Wl, nullptr, p_lvec, 3 * N, HDIM, HDIM);

    // 6) vector activation epilogue
    combine_kernel<<<2048, 128>>>(p_lvec, Wg, dvec, N);
}